// round 17
// baseline (speedup 1.0000x reference)
#include <cuda_runtime.h>
#include <cuda_bf16.h>
#include <math.h>
#include <stdint.h>

// ---------------------------------------------------------------------------
// MambaBlock: B=2, S=1024, D_MODEL=1024, D_INNER=2048, D_STATE=16, D_CONV=4
// Round 17: conv+silu fused INTO xproj (one xz pass, xconv_t written once,
// partials accumulated from smem); both weight cvt+transposes in one launch.
// GEMMs (bf16 ldmatrix BK=64) and 3-phase scan unchanged.
// ---------------------------------------------------------------------------

#define TOK 2048
#define DM  1024
#define DI  2048
#define DS  16
#define NXP 33
#define SEQL 1024
#define NCHUNK 16
#define CLEN 64
#define KSPLIT 32
#define KSEG (DI / KSPLIT)   // 64

__device__ __nv_bfloat16 g_xn[TOK * DM];
__device__ __nv_bfloat16 g_y[TOK * DI];
__device__ __nv_bfloat16 g_WinT[2 * DI * DM];   // [4096,1024] bf16
__device__ __nv_bfloat16 g_WoutT[DM * DI];      // [1024,2048] bf16
__device__ float g_xz[TOK * 2 * DI];
__device__ float g_xconv_t[TOK * DI];      // [b][ch][t]
__device__ float g_ssm[TOK * NXP];
__device__ float g_xp[KSPLIT * NXP * TOK];
__device__ float g_P[2 * NCHUNK * DI * DS];
__device__ float g_hL[2 * NCHUNK * DI * DS];
__device__ float g_h0[2 * NCHUNK * DI * DS];

// ------------------------------ helpers ------------------------------------
__device__ __forceinline__ uint32_t smem_u32(const void* p) {
    uint32_t a;
    asm("{ .reg .u64 t; cvta.to.shared.u64 t, %1; cvt.u32.u64 %0, t; }" : "=r"(a) : "l"(p));
    return a;
}
__device__ __forceinline__ void cp_async16(uint32_t dst, const void* src) {
    asm volatile("cp.async.cg.shared.global [%0], [%1], 16;" :: "r"(dst), "l"(src));
}
__device__ __forceinline__ void cp_commit() {
    asm volatile("cp.async.commit_group;");
}
__device__ __forceinline__ void ldsm_x4(uint32_t* r, uint32_t addr) {
    asm volatile("ldmatrix.sync.aligned.m8n8.x4.shared.b16 {%0,%1,%2,%3}, [%4];"
        : "=r"(r[0]), "=r"(r[1]), "=r"(r[2]), "=r"(r[3]) : "r"(addr));
}
__device__ __forceinline__ void mma_bf16(float* d, const uint32_t* a, const uint32_t* b) {
    asm volatile(
        "mma.sync.aligned.m16n8k16.row.col.f32.bf16.bf16.f32 "
        "{%0,%1,%2,%3}, {%4,%5,%6,%7}, {%8,%9}, {%0,%1,%2,%3};"
        : "+f"(d[0]), "+f"(d[1]), "+f"(d[2]), "+f"(d[3])
        : "r"(a[0]), "r"(a[1]), "r"(a[2]), "r"(a[3]), "r"(b[0]), "r"(b[1]));
}
__device__ __forceinline__ float softplus_f(float x) {
    return (x > 15.f) ? x : log1pf(expf(x));
}
__device__ __forceinline__ float silu_f(float x) {
    return x / (1.f + __expf(-x));
}

// ------------------------- mma.sync bf16 GEMM ------------------------------
#define SAb 72                      // bf16 row stride (144 B) for 64-k tile
#define TILEB (128 * SAb)
#define GSMEMB (3 * 2 * TILEB * 2)

template <bool RES>
__global__ void __launch_bounds__(256, 2) gemm_bf16_kernel(
    const __nv_bfloat16* __restrict__ A, const __nv_bfloat16* __restrict__ Bt,
    const float* __restrict__ Rsd, float* __restrict__ C,
    int Nout, int K)
{
    extern __shared__ __align__(16) __nv_bfloat16 smemb[];
    __nv_bfloat16* As = smemb;
    __nv_bfloat16* Bs = smemb + 3 * TILEB;
    const uint32_t as_u = smem_u32(As);
    const uint32_t bs_u = smem_u32(Bs);

    const int tid = threadIdx.x;
    const int wid = tid >> 5;
    const int lane = tid & 31;
    const int wr = wid & 3;
    const int wc = wid >> 2;
    const int g = lane >> 2;
    const int tig = lane & 3;

    const int row0 = blockIdx.y * 128;
    const int col0 = blockIdx.x * 128;
    const int KT = K >> 6;

    const int a_row = (lane & 15);
    const int a_kh = (lane >> 4) << 3;
    const int b_nrow = ((lane >> 4) << 3) + (lane & 7);
    const int b_kh = ((lane >> 3) & 1) << 3;

    float acc[2][8][4];
    #pragma unroll
    for (int i = 0; i < 2; i++)
        #pragma unroll
        for (int j = 0; j < 8; j++)
            #pragma unroll
            for (int q = 0; q < 4; q++) acc[i][j][q] = 0.f;

    auto load_stage = [&](int i, int st) {
        const int k0 = i << 6;
        #pragma unroll
        for (int it = 0; it < 4; ++it) {
            const int s = it * 256 + tid;
            const int r = s >> 3;
            const int c = (s & 7) << 3;
            cp_async16(as_u + (st * TILEB + r * SAb + c) * 2,
                       &A[(size_t)(row0 + r) * K + k0 + c]);
            cp_async16(bs_u + (st * TILEB + r * SAb + c) * 2,
                       &Bt[(size_t)(col0 + r) * K + k0 + c]);
        }
    };

    load_stage(0, 0); cp_commit();
    load_stage(1, 1); cp_commit();

    for (int i = 0; i < KT; ++i) {
        asm volatile("cp.async.wait_group 1;" ::: "memory");
        __syncthreads();
        if (i + 2 < KT) load_stage(i + 2, (i + 2) % 3);
        cp_commit();

        const uint32_t abase = as_u + ((i % 3) * TILEB) * 2;
        const uint32_t bbase = bs_u + ((i % 3) * TILEB) * 2;
        #pragma unroll
        for (int ks = 0; ks < 4; ++ks) {
            const int kk = (ks << 4);
            uint32_t afr[2][4];
            #pragma unroll
            for (int mt = 0; mt < 2; ++mt) {
                const int rb = wr * 32 + mt * 16;
                ldsm_x4(afr[mt], abase + ((rb + a_row) * SAb + kk + a_kh) * 2);
            }
            uint32_t bfr[4][4];
            #pragma unroll
            for (int p = 0; p < 4; ++p) {
                const int nb = wc * 64 + p * 16;
                ldsm_x4(bfr[p], bbase + ((nb + b_nrow) * SAb + kk + b_kh) * 2);
            }
            #pragma unroll
            for (int mt = 0; mt < 2; ++mt)
                #pragma unroll
                for (int nt = 0; nt < 8; ++nt)
                    mma_bf16(acc[mt][nt], afr[mt], &bfr[nt >> 1][(nt & 1) * 2]);
        }
    }

    #pragma unroll
    for (int mt = 0; mt < 2; ++mt) {
        const int r0 = row0 + wr * 32 + mt * 16 + g;
        #pragma unroll
        for (int nt = 0; nt < 8; ++nt) {
            const int c = col0 + wc * 64 + nt * 8 + tig * 2;
            float2 v0 = make_float2(acc[mt][nt][0], acc[mt][nt][1]);
            float2 v1 = make_float2(acc[mt][nt][2], acc[mt][nt][3]);
            if (RES) {
                float2 r0v = *reinterpret_cast<const float2*>(&Rsd[(size_t)r0 * Nout + c]);
                float2 r1v = *reinterpret_cast<const float2*>(&Rsd[(size_t)(r0 + 8) * Nout + c]);
                v0.x += r0v.x; v0.y += r0v.y;
                v1.x += r1v.x; v1.y += r1v.y;
            }
            *reinterpret_cast<float2*>(&C[(size_t)r0 * Nout + c]) = v0;
            *reinterpret_cast<float2*>(&C[(size_t)(r0 + 8) * Nout + c]) = v1;
        }
    }
}

// ---------- both weight converts+transposes in ONE launch ------------------
// bid < 4096: W_in [1024,4096] -> WinT [4096,1024]
// else      : W_out [2048,1024] -> WoutT [1024,2048]
__global__ void __launch_bounds__(256) cvtT_both_kernel(
    const float* __restrict__ Win, __nv_bfloat16* __restrict__ WinT,
    const float* __restrict__ Wout, __nv_bfloat16* __restrict__ WoutT)
{
    __shared__ float tile[32][33];
    const int x = threadIdx.x, y = threadIdx.y;
    const float* in;
    __nv_bfloat16* out;
    int R, Ccols, c0, r0;
    const int bid = blockIdx.x;
    if (bid < 4096) {                 // W_in: 128 col-tiles x 32 row-tiles
        in = Win; out = WinT; R = DM; Ccols = 2 * DI;
        c0 = (bid & 127) * 32; r0 = (bid >> 7) * 32;
    } else {                          // W_out: 32 col-tiles x 64 row-tiles
        const int b2 = bid - 4096;
        in = Wout; out = WoutT; R = DI; Ccols = DM;
        c0 = (b2 & 31) * 32; r0 = (b2 >> 5) * 32;
    }
    #pragma unroll
    for (int j = 0; j < 32; j += 8)
        tile[y + j][x] = in[(size_t)(r0 + y + j) * Ccols + c0 + x];
    __syncthreads();
    #pragma unroll
    for (int j = 0; j < 32; j += 8)
        out[(size_t)(c0 + y + j) * R + r0 + x] = __float2bfloat16(tile[x][y + j]);
}

// ------------------------------ rmsnorm (bf16 out) -------------------------
__global__ void __launch_bounds__(256) rmsnorm_kernel(
    const float* __restrict__ x, const float* __restrict__ w,
    __nv_bfloat16* __restrict__ xn)
{
    const int token = blockIdx.x;
    const int tid = threadIdx.x;
    const float4* x4 = reinterpret_cast<const float4*>(x + (size_t)token * DM);
    float4 v = x4[tid];
    float s = v.x * v.x + v.y * v.y + v.z * v.z + v.w * v.w;
    __shared__ float red[8];
    #pragma unroll
    for (int o = 16; o; o >>= 1) s += __shfl_xor_sync(0xffffffffu, s, o);
    if ((tid & 31) == 0) red[tid >> 5] = s;
    __syncthreads();
    if (tid < 32) {
        float t = (tid < 8) ? red[tid] : 0.f;
        #pragma unroll
        for (int o = 4; o; o >>= 1) t += __shfl_xor_sync(0xffffffffu, t, o);
        if (tid == 0) red[0] = t;
    }
    __syncthreads();
    const float ms = red[0] * (1.f / (float)DM);
    const float r = rsqrtf(ms + 1.1920928955078125e-07f);
    const float4* w4 = reinterpret_cast<const float4*>(w);
    float4 wv = w4[tid];
    __nv_bfloat162* o2 = reinterpret_cast<__nv_bfloat162*>(xn + (size_t)token * DM) + tid * 2;
    o2[0] = __floats2bfloat162_rn(v.x * r * wv.x, v.y * r * wv.y);
    o2[1] = __floats2bfloat162_rn(v.z * r * wv.z, v.w * r * wv.w);
}

// ------------- fused conv+silu+xproj (32-way k-split) ----------------------
// Grid (TOK/128, KSPLIT), block 128.  Each block: 128 tokens x 64 channels.
// Loads xz tile once (with conv halo), computes conv+silu into smem,
// writes xconv_t, accumulates NXP partials from smem.
// SMEM floats: sxz[131][65] | sxc[64][129] | Wbuf[64*33] | scw[256] | scb[64]
#define SXZ_N (131 * 65)
#define SXC_N (64 * 129)
#define XPSMEM ((SXZ_N + SXC_N + KSEG * NXP + 256 + 64) * 4)

__global__ void __launch_bounds__(128) xproj_conv_kernel(
    const float* __restrict__ xz, const float* __restrict__ W,
    const float* __restrict__ cw, const float* __restrict__ cb,
    float* __restrict__ xconv_t, float* __restrict__ part)
{
    extern __shared__ float sm[];
    float* sxz = sm;                       // [131][65] rows t0-3..t0+127
    float* sxc = sm + SXZ_N;               // [64][129]
    float* Wbuf = sxc + SXC_N;             // [64*33] contiguous rows
    float* scw = Wbuf + KSEG * NXP;        // [64][4]
    float* scb = scw + 256;                // [64]

    const int tid = threadIdx.x;
    const int ks = blockIdx.y;
    const int ch0 = ks * KSEG;
    const int t0 = blockIdx.x * 128;
    const int b = t0 >> 10;
    const int t0b = t0 & (SEQL - 1);

    // weights (W rows for ch0..ch0+63 are contiguous)
    for (int i = tid; i < KSEG * NXP; i += 128)
        Wbuf[i] = W[(size_t)ch0 * NXP + i];
    if (tid < 256) {} // (scw loaded below; 128 threads -> 2 passes)
    for (int i = tid; i < 256; i += 128) scw[i] = cw[ch0 * 4 + i];
    if (tid < 64) scb[tid] = cb[ch0 + tid];

    // xz tile with 3-row halo (zero before batch start)
    for (int i = tid; i < 131 * 64; i += 128) {
        const int r = i >> 6, c = i & 63;
        const int t = t0b + r - 3;
        sxz[r * 65 + c] = (t >= 0)
            ? xz[(size_t)(b * SEQL + t) * (2 * DI) + ch0 + c] : 0.f;
    }
    __syncthreads();

    // conv + silu -> sxc[c][t], and write xconv_t
    for (int i = tid; i < 64 * 128; i += 128) {
        const int c = i >> 7, t = i & 127;
        float acc = scb[c];
        #pragma unroll
        for (int k = 0; k < 4; ++k)
            acc = fmaf(sxz[(t + k) * 65 + c], scw[c * 4 + k], acc);
        const float v = silu_f(acc);
        sxc[c * 129 + t] = v;
        xconv_t[((size_t)b * DI + ch0 + c) * SEQL + t0b + t] = v;
    }
    __syncthreads();

    // xproj partials: thread = one token
    float acc[NXP];
    #pragma unroll
    for (int c = 0; c < NXP; ++c) acc[c] = 0.f;
    #pragma unroll 4
    for (int kr = 0; kr < KSEG; ++kr) {
        const float xv = sxc[kr * 129 + tid];
        #pragma unroll
        for (int c = 0; c < NXP; ++c)
            acc[c] = fmaf(xv, Wbuf[kr * NXP + c], acc[c]);
    }
    const int tok = t0 + tid;
    #pragma unroll
    for (int c = 0; c < NXP; ++c)
        part[((size_t)ks * NXP + c) * TOK + tok] = acc[c];
}

__global__ void __launch_bounds__(256) xproj_reduce_kernel(
    const float* __restrict__ part, float* __restrict__ ssm)
{
    const int idx = blockIdx.x * 256 + threadIdx.x;
    if (idx >= NXP * TOK) return;
    const int c = idx / TOK;
    const int tok = idx - c * TOK;
    float s = 0.f;
    #pragma unroll
    for (int ks = 0; ks < KSPLIT; ++ks)
        s += part[((size_t)ks * NXP + c) * TOK + tok];
    ssm[(size_t)tok * NXP + c] = s;
}

// --------------------------- scan phase A ----------------------------------
__global__ void __launch_bounds__(256) scan_a_kernel(
    const float* __restrict__ ssm, const float* __restrict__ xconv_t,
    const float* __restrict__ A_log, const float* __restrict__ W_dt,
    const float* __restrict__ b_dt, float* __restrict__ Pout,
    float* __restrict__ hLout)
{
    __shared__ float sB[CLEN][DS];
    __shared__ float sxc[16][CLEN];
    __shared__ float sdt[16][CLEN];
    __shared__ float sdtraw[CLEN];
    __shared__ float swdt[16], sbdt[16];

    const int ch0 = blockIdx.x * 16;
    const int chunk = blockIdx.y;
    const int b = blockIdx.z;
    const int tid = threadIdx.x;
    const int chl = tid >> 4;
    const int n = tid & 15;
    const int ch = ch0 + chl;
    const int t0 = chunk * CLEN;

    for (int i = tid; i < CLEN * DS; i += 256) {
        const int t = i >> 4, nn = i & 15;
        sB[t][nn] = ssm[(size_t)(b * SEQL + t0 + t) * NXP + 1 + nn];
    }
    for (int i = tid; i < 16 * CLEN; i += 256) {
        const int r = i >> 6, t = i & 63;
        sxc[r][t] = xconv_t[((size_t)b * DI + ch0 + r) * SEQL + t0 + t];
    }
    if (tid < CLEN) sdtraw[tid] = ssm[(size_t)(b * SEQL + t0 + tid) * NXP];
    if (tid >= 224 && tid < 240) {
        swdt[tid - 224] = W_dt[ch0 + tid - 224];
        sbdt[tid - 224] = b_dt[ch0 + tid - 224];
    }
    __syncthreads();
    for (int i = tid; i < 16 * CLEN; i += 256) {
        const int r = i >> 6, t = i & 63;
        sdt[r][t] = softplus_f(fmaf(sdtraw[t], swdt[r], sbdt[r]));
    }
    __syncthreads();

    const float An = -expf(A_log[ch * DS + n]);
    float h = 0.f, P = 1.f;
    #pragma unroll 4
    for (int t = 0; t < CLEN; ++t) {
        const float dtv = sdt[chl][t];
        const float ab = __expf(dtv * An);
        h = fmaf(ab, h, dtv * sxc[chl][t] * sB[t][n]);
        P *= ab;
    }
    const size_t idx = (((size_t)b * NCHUNK + chunk) * DI + ch) * DS + n;
    Pout[idx] = P;
    hLout[idx] = h;
}

// --------------------------- scan phase B ----------------------------------
__global__ void __launch_bounds__(256) scan_b_kernel(
    const float* __restrict__ P, const float* __restrict__ hL,
    float* __restrict__ h0)
{
    const int gid = blockIdx.x * 256 + threadIdx.x;
    const int b = gid / (DI * DS);
    const int r = gid - b * (DI * DS);
    float h = 0.f;
    #pragma unroll
    for (int c = 0; c < NCHUNK; ++c) {
        const size_t idx = ((size_t)(b * NCHUNK + c)) * (DI * DS) + r;
        h0[idx] = h;
        h = fmaf(P[idx], h, hL[idx]);
    }
}

// --------------------------- scan phase C + gate (bf16 y out) --------------
__global__ void __launch_bounds__(256) scan_c_kernel(
    const float* __restrict__ ssm, const float* __restrict__ xconv_t,
    const float* __restrict__ A_log, const float* __restrict__ W_dt,
    const float* __restrict__ b_dt, const float* __restrict__ Dp,
    const float* __restrict__ h0, const float* __restrict__ xz,
    __nv_bfloat16* __restrict__ y)
{
    __shared__ float sB[CLEN][DS];
    __shared__ float sC[CLEN][DS];
    __shared__ float sxc[16][CLEN];
    __shared__ float sdt[16][CLEN];
    __shared__ float sy[16][CLEN + 1];
    __shared__ float sdtraw[CLEN];
    __shared__ float swdt[16], sbdt[16];

    const int ch0 = blockIdx.x * 16;
    const int chunk = blockIdx.y;
    const int b = blockIdx.z;
    const int tid = threadIdx.x;
    const int chl = tid >> 4;
    const int n = tid & 15;
    const int ch = ch0 + chl;
    const int t0 = chunk * CLEN;

    for (int i = tid; i < CLEN * DS; i += 256) {
        const int t = i >> 4, nn = i & 15;
        const float* row = &ssm[(size_t)(b * SEQL + t0 + t) * NXP];
        sB[t][nn] = row[1 + nn];
        sC[t][nn] = row[1 + DS + nn];
    }
    for (int i = tid; i < 16 * CLEN; i += 256) {
        const int r = i >> 6, t = i & 63;
        sxc[r][t] = xconv_t[((size_t)b * DI + ch0 + r) * SEQL + t0 + t];
    }
    if (tid < CLEN) sdtraw[tid] = ssm[(size_t)(b * SEQL + t0 + tid) * NXP];
    if (tid >= 224 && tid < 240) {
        swdt[tid - 224] = W_dt[ch0 + tid - 224];
        sbdt[tid - 224] = b_dt[ch0 + tid - 224];
    }
    __syncthreads();
    for (int i = tid; i < 16 * CLEN; i += 256) {
        const int r = i >> 6, t = i & 63;
        sdt[r][t] = softplus_f(fmaf(sdtraw[t], swdt[r], sbdt[r]));
    }
    __syncthreads();

    const float An = -expf(A_log[ch * DS + n]);
    const float Dch = Dp[ch];
    float h = h0[(((size_t)b * NCHUNK + chunk) * DI + ch) * DS + n];

    #pragma unroll 4
    for (int t = 0; t < CLEN; ++t) {
        const float dtv = sdt[chl][t];
        const float xcv = sxc[chl][t];
        const float ab = __expf(dtv * An);
        h = fmaf(ab, h, dtv * xcv * sB[t][n]);
        float p = h * sC[t][n];
        p += __shfl_xor_sync(0xffffffffu, p, 1);
        p += __shfl_xor_sync(0xffffffffu, p, 2);
        p += __shfl_xor_sync(0xffffffffu, p, 4);
        p += __shfl_xor_sync(0xffffffffu, p, 8);
        if (n == 0) sy[chl][t] = fmaf(xcv, Dch, p);
    }
    __syncthreads();

    for (int i = tid; i < CLEN * 16; i += 256) {
        const int t = i >> 4, c = i & 15;
        const int tok = b * SEQL + t0 + t;
        const float z = xz[(size_t)tok * (2 * DI) + DI + ch0 + c];
        y[(size_t)tok * DI + ch0 + c] = __float2bfloat16(sy[c][t] * silu_f(z));
    }
}

// ---------------------------------------------------------------------------
extern "C" void kernel_launch(void* const* d_in, const int* in_sizes, int n_in,
                              void* d_out, int out_size)
{
    const float* x      = (const float*)d_in[0];
    const float* W_in   = (const float*)d_in[1];
    const float* conv_w = (const float*)d_in[2];
    const float* conv_b = (const float*)d_in[3];
    const float* W_xproj= (const float*)d_in[4];
    const float* W_dt   = (const float*)d_in[5];
    const float* b_dt   = (const float*)d_in[6];
    const float* A_log  = (const float*)d_in[7];
    const float* Dp     = (const float*)d_in[8];
    const float* W_out  = (const float*)d_in[9];
    const float* norm_w = (const float*)d_in[10];
    float* out = (float*)d_out;

    __nv_bfloat16 *p_xn, *p_y, *p_WinT, *p_WoutT;
    float *p_xz, *p_xct, *p_ssm, *p_xp, *p_P, *p_hL, *p_h0;
    cudaGetSymbolAddress((void**)&p_xn, g_xn);
    cudaGetSymbolAddress((void**)&p_y, g_y);
    cudaGetSymbolAddress((void**)&p_WinT, g_WinT);
    cudaGetSymbolAddress((void**)&p_WoutT, g_WoutT);
    cudaGetSymbolAddress((void**)&p_xz, g_xz);
    cudaGetSymbolAddress((void**)&p_xct, g_xconv_t);
    cudaGetSymbolAddress((void**)&p_ssm, g_ssm);
    cudaGetSymbolAddress((void**)&p_xp, g_xp);
    cudaGetSymbolAddress((void**)&p_P, g_P);
    cudaGetSymbolAddress((void**)&p_hL, g_hL);
    cudaGetSymbolAddress((void**)&p_h0, g_h0);

    static bool attr_done = false;
    if (!attr_done) {
        cudaFuncSetAttribute(gemm_bf16_kernel<false>,
                             cudaFuncAttributeMaxDynamicSharedMemorySize, GSMEMB);
        cudaFuncSetAttribute(gemm_bf16_kernel<true>,
                             cudaFuncAttributeMaxDynamicSharedMemorySize, GSMEMB);
        cudaFuncSetAttribute(xproj_conv_kernel,
                             cudaFuncAttributeMaxDynamicSharedMemorySize, XPSMEM);
        attr_done = true;
    }

    // 0) both weight cvt+transposes (one launch)
    cvtT_both_kernel<<<4096 + 2048, dim3(32, 8)>>>(W_in, p_WinT, W_out, p_WoutT);

    // 1) rmsnorm -> bf16 xn
    rmsnorm_kernel<<<TOK, 256>>>(x, norm_w, p_xn);

    // 2) xz = xn @ W_in
    gemm_bf16_kernel<false><<<dim3((2 * DI) / 128, TOK / 128), 256, GSMEMB>>>(
        p_xn, p_WinT, nullptr, p_xz, 2 * DI, DM);

    // 3) fused conv+silu+xproj (writes xconv_t + partials)
    xproj_conv_kernel<<<dim3(TOK / 128, KSPLIT), 128, XPSMEM>>>(
        p_xz, W_xproj, conv_w, conv_b, p_xct, p_xp);
    xproj_reduce_kernel<<<(NXP * TOK + 255) / 256, 256>>>(p_xp, p_ssm);

    // 4) 3-phase scan (softplus in staging), gate fused into phase C
    scan_a_kernel<<<dim3(DI / 16, NCHUNK, 2), 256>>>(
        p_ssm, p_xct, A_log, W_dt, b_dt, p_P, p_hL);
    scan_b_kernel<<<(2 * DI * DS) / 256, 256>>>(p_P, p_hL, p_h0);
    scan_c_kernel<<<dim3(DI / 16, NCHUNK, 2), 256>>>(
        p_ssm, p_xct, A_log, W_dt, b_dt, Dp, p_h0, p_xz, p_y);

    // 5) out = x + y @ W_out
    gemm_bf16_kernel<true><<<dim3(DM / 128, TOK / 128), 256, GSMEMB>>>(
        p_y, p_WoutT, x, out, DM, DI);
}